// round 12
// baseline (speedup 1.0000x reference)
#include <cuda_runtime.h>

#define Bq 128
#define Nn 64
#define Dd 64
#define Aa 12
#define Hh 128
#define Ee 4032
#define NITERS 8
#define TE 64   // edges per gemm block

typedef unsigned long long ull;

// -------- device scratch (no allocations allowed) --------
__device__ __align__(16) float g_edge_vals[74317824];   // B*E*A*A, PRE-SCALED by 1/E
__device__ __align__(16) float g_X1[Bq*Nn*Hh];
__device__ __align__(16) float g_X2[Bq*Nn*Hh];
__device__ float g_node_vals[Bq*Nn*Aa];
__device__ float g_q[Bq*Nn*Aa];
__device__ __align__(16) float g_msg_forw[Bq*Ee*Aa];
__device__ __align__(16) float g_msg_back[Bq*Ee*Aa];
__device__ float g_qmax[Bq];

// ---------------------------------------------------------
// K0: node MLP + per-node halves of edge layer-1 (X1, X2)
// ---------------------------------------------------------
__global__ void k_node(const float* __restrict__ obs, const float* __restrict__ W1n,
                       const float* __restrict__ b1n, const float* __restrict__ W2n,
                       const float* __restrict__ b2n, const float* __restrict__ W1e) {
    int row0 = blockIdx.x * 8;
    int t = threadIdx.x;
    __shared__ float so[8][64];
    __shared__ float sh[8][128];
    for (int i = t; i < 512; i += 128) so[i >> 6][i & 63] = obs[row0 * 64 + i];
    __syncthreads();
    for (int r = 0; r < 8; r++) {
        float s1 = b1n[t], x1 = 0.f, x2 = 0.f;
#pragma unroll 8
        for (int d = 0; d < 64; d++) {
            float o = so[r][d];
            s1 = fmaf(o, W1n[d * 128 + t], s1);
            x1 = fmaf(o, W1e[d * 128 + t], x1);
            x2 = fmaf(o, W1e[(64 + d) * 128 + t], x2);
        }
        sh[r][t] = fmaxf(s1, 0.f);
        g_X1[(row0 + r) * 128 + t] = x1;
        g_X2[(row0 + r) * 128 + t] = x2;
    }
    __syncthreads();
    if (t < 96) {
        int r = t / 12, a = t - r * 12;
        float nv = b2n[a];
#pragma unroll 8
        for (int k = 0; k < 128; k++) nv = fmaf(sh[r][k], W2n[k * 12 + a], nv);
        g_node_vals[(row0 + r) * 12 + a] = nv;
    }
}

// ---------------------------------------------------------
// K1: edge layer-2 GEMM, f32x2. 384 thr, 8 rows x 3 cols.
// Thread map rg=tid%8, cg=tid/8: warp lanes share 4 consecutive
// cg -> ws loads are 1-wavefront; hv LDS.128 spread = 2 wavefronts.
// 64-edge tile -> 2 blocks/SM. Output pre-scaled by 1/E.
// ---------------------------------------------------------
__global__ void __launch_bounds__(384, 2)
k_edge_gemm(const int* __restrict__ ef, const int* __restrict__ et,
            const float* __restrict__ b1e, const float* __restrict__ W2e,
            const float* __restrict__ b2e, int b_off) {
    extern __shared__ float sm[];
    float* Wsh = sm;                 // 128*144 floats
    float* hT  = sm + 18432;         // 128*68 floats (pitch 68: 272B, 16B-aligned per k)
    __shared__ int sf[TE], st2[TE];
    int b = b_off + blockIdx.y;
    int e0 = blockIdx.x * TE;
    int tid = threadIdx.x;

    if (tid < TE) { sf[tid] = ef[e0 + tid]; st2[tid] = et[e0 + tid]; }
    {
        const float4* W4 = (const float4*)W2e;
        float4* Ws4 = (float4*)Wsh;
        for (int i = tid; i < 4608; i += 384) Ws4[i] = W4[i];
    }
    __syncthreads();

    for (int idx = tid; idx < 8192; idx += 384) {
        int el = idx >> 7, k = idx & 127;
        float v = g_X1[(b * Nn + sf[el]) * Hh + k] + g_X2[(b * Nn + st2[el]) * Hh + k] + b1e[k];
        hT[k * 68 + el] = fmaxf(v, 0.f);
    }
    __syncthreads();

    int rg = tid & 7;      // rows rg*8 .. rg*8+7   (8 distinct per warp)
    int cg = tid >> 3;     // cols cg*3 .. cg*3+2   (4 distinct per warp)

    ull acc[4][3];
#pragma unroll
    for (int j = 0; j < 4; j++)
#pragma unroll
        for (int c = 0; c < 3; c++) acc[j][c] = 0ull;

    const float* hbase = hT + rg * 8;
    const float* wbase = Wsh + cg * 3;

    ulonglong2 hA[2], hB[2];   // hA: rows 0-3 (2 pairs), hB: rows 4-7
    float ws[2][3];
    hA[0] = *(const ulonglong2*)(hbase);
    hB[0] = *(const ulonglong2*)(hbase + 4);
#pragma unroll
    for (int c = 0; c < 3; c++) ws[0][c] = wbase[c];

#pragma unroll 8
    for (int k = 0; k < 128; k++) {
        int cur = k & 1, nxt = cur ^ 1;
        if (k < 127) {
            hA[nxt] = *(const ulonglong2*)(hbase + (k + 1) * 68);
            hB[nxt] = *(const ulonglong2*)(hbase + (k + 1) * 68 + 4);
#pragma unroll
            for (int c = 0; c < 3; c++) ws[nxt][c] = wbase[(k + 1) * 144 + c];
        }
        ull wv[3];
#pragma unroll
        for (int c = 0; c < 3; c++)
            asm("mov.b64 %0, {%1, %1};" : "=l"(wv[c]) : "f"(ws[cur][c]));
        ull hv0 = hA[cur].x, hv1 = hA[cur].y, hv2 = hB[cur].x, hv3 = hB[cur].y;
#pragma unroll
        for (int c = 0; c < 3; c++) {
            asm("fma.rn.f32x2 %0, %1, %2, %0;" : "+l"(acc[0][c]) : "l"(hv0), "l"(wv[c]));
            asm("fma.rn.f32x2 %0, %1, %2, %0;" : "+l"(acc[1][c]) : "l"(hv1), "l"(wv[c]));
            asm("fma.rn.f32x2 %0, %1, %2, %0;" : "+l"(acc[2][c]) : "l"(hv2), "l"(wv[c]));
            asm("fma.rn.f32x2 %0, %1, %2, %0;" : "+l"(acc[3][c]) : "l"(hv3), "l"(wv[c]));
        }
    }

    float bb[3];
#pragma unroll
    for (int c = 0; c < 3; c++) bb[c] = b2e[cg * 3 + c];
    const float invE = 1.f / Ee;

    size_t base = ((size_t)b * Ee + e0) * 144 + cg * 3;
#pragma unroll
    for (int j = 0; j < 4; j++) {
        int row = rg * 8 + 2 * j;
#pragma unroll
        for (int c = 0; c < 3; c++) {
            float lo, hi;
            asm("mov.b64 {%0, %1}, %2;" : "=f"(lo), "=f"(hi) : "l"(acc[j][c]));
            g_edge_vals[base + (size_t)row * 144 + c]       = (lo + bb[c]) * invE;
            g_edge_vals[base + (size_t)(row + 1) * 144 + c] = (hi + bb[c]) * invE;
        }
    }
}

// ---------------------------------------------------------
// K4: message update, register/shuffle version (R7).
// ---------------------------------------------------------
__global__ void __launch_bounds__(512)
k_msg(const int* __restrict__ ef, const int* __restrict__ et, int first) {
    __shared__ float sev[32 * 144 + 160];
    int b = blockIdx.y;
    int tid = threadIdx.x;
    int elb = tid >> 4;
    int sub = tid & 15;
    int e = blockIdx.x * 32 + elb;
    unsigned g = (tid & 31) & ~15u;

    size_t evbase = ((size_t)b * Ee + e) * 144;
    size_t mi = ((size_t)b * Ee + e) * 12 + sub;
    float r[12];
    float su = 0.f, sv = 0.f;
    if (sub < 12) {
        float4 r0 = *(const float4*)&g_edge_vals[evbase + sub * 12];
        float4 r1 = *(const float4*)&g_edge_vals[evbase + sub * 12 + 4];
        float4 r2 = *(const float4*)&g_edge_vals[evbase + sub * 12 + 8];
        r[0]=r0.x; r[1]=r0.y; r[2]=r0.z; r[3]=r0.w;
        r[4]=r1.x; r[5]=r1.y; r[6]=r1.z; r[7]=r1.w;
        r[8]=r2.x; r[9]=r2.y; r[10]=r2.z; r[11]=r2.w;
        int f = ef[e], t = et[e];
        su = g_q[(b * Nn + f) * 12 + sub];
        sv = g_q[(b * Nn + t) * 12 + sub];
        if (!first) { su -= g_msg_back[mi]; sv -= g_msg_forw[mi]; }
        float4* sp = (float4*)&sev[elb * 144 + sub * 12];
        sp[0] = r0; sp[1] = r1; sp[2] = r2;
    } else {
#pragma unroll
        for (int x = 0; x < 12; x++) r[x] = 0.f;
    }
    __syncwarp();

    float mf = -3.4e38f, mb = -3.4e38f;
    const float* colp = &sev[elb * 144 + sub];
#pragma unroll
    for (int x = 0; x < 12; x++) {
        float sux = __shfl_sync(0xffffffffu, su, g + x);
        float svx = __shfl_sync(0xffffffffu, sv, g + x);
        mb = fmaxf(mb, svx + r[x]);
        mf = fmaxf(mf, sux + colp[x * 12]);
    }
    float sf = (sub < 12) ? mf : 0.f;
    float sb = (sub < 12) ? mb : 0.f;
#pragma unroll
    for (int o = 8; o; o >>= 1) {
        sf += __shfl_xor_sync(0xffffffffu, sf, o);
        sb += __shfl_xor_sync(0xffffffffu, sb, o);
    }
    if (sub < 12) {
        g_msg_forw[mi] = mf - sf * (1.f / 12.f);
        g_msg_back[mi] = mb - sb * (1.f / 12.f);
    }
}

// ---------------------------------------------------------
// K5: fused q-update + argmax + eval (shuffle reductions).
// ---------------------------------------------------------
__global__ void __launch_bounds__(1024)
k_qe(const int* __restrict__ ef, const int* __restrict__ et,
     float* __restrict__ out, int first) {
    int b = blockIdx.x, tid = threadIdx.x;
    int w = tid >> 5, lane = tid & 31;
    __shared__ float snv[768];
    __shared__ int sa[64];
    __shared__ float red[32];
    __shared__ float red2[2];
    __shared__ int flag;
    for (int i = tid; i < 768; i += 1024) snv[i] = g_node_vals[b * 768 + i];
    __syncthreads();

    if (first) {
        if (tid < 768) g_q[b * 768 + tid] = snv[tid] * (1.f / Nn);
        if (tid < 64) {
            float best = -3.4e38f; int ba = 0;
#pragma unroll
            for (int a = 0; a < 12; a++) {
                float v = snv[tid * 12 + a];
                if (v > best) { best = v; ba = a; }
            }
            sa[tid] = ba;
        }
    } else {
#pragma unroll
        for (int nn = 0; nn < 2; nn++) {
            int n = w * 2 + nn;
            float acc[12];
#pragma unroll
            for (int a = 0; a < 12; a++) acc[a] = 0.f;

            size_t mbb = ((size_t)b * Ee + n * 63) * 12;
            for (int m = lane; m < 63; m += 32) {
                const float4* p = (const float4*)&g_msg_back[mbb + m * 12];
                float4 p0 = p[0], p1 = p[1], p2 = p[2];
                acc[0] += p0.x; acc[1] += p0.y; acc[2]  += p0.z; acc[3]  += p0.w;
                acc[4] += p1.x; acc[5] += p1.y; acc[6]  += p1.z; acc[7]  += p1.w;
                acc[8] += p2.x; acc[9] += p2.y; acc[10] += p2.z; acc[11] += p2.w;
            }
            for (int i = lane; i < 64; i += 32) {
                if (i == n) continue;
                int e = i * 63 + n - (n > i ? 1 : 0);
                const float4* p = (const float4*)&g_msg_forw[((size_t)b * Ee + e) * 12];
                float4 p0 = p[0], p1 = p[1], p2 = p[2];
                acc[0] += p0.x; acc[1] += p0.y; acc[2]  += p0.z; acc[3]  += p0.w;
                acc[4] += p1.x; acc[5] += p1.y; acc[6]  += p1.z; acc[7]  += p1.w;
                acc[8] += p2.x; acc[9] += p2.y; acc[10] += p2.z; acc[11] += p2.w;
            }
#pragma unroll
            for (int off = 16; off; off >>= 1)
#pragma unroll
                for (int a = 0; a < 12; a++) acc[a] += __shfl_down_sync(0xffffffffu, acc[a], off);

            if (lane == 0) {
                float best = -3.4e38f; int ba = 0;
#pragma unroll
                for (int a = 0; a < 12; a++) {
                    float qa = snv[n * 12 + a] * (1.f / Nn) + acc[a];
                    g_q[(b * 64 + n) * 12 + a] = qa;
                    if (qa > best) { best = qa; ba = a; }
                }
                sa[n] = ba;
            }
        }
    }
    __syncthreads();

    float s = 0.f;
#pragma unroll
    for (int e = tid; e < Ee; e += 1024)
        s += g_edge_vals[((size_t)b * Ee + e) * 144 + sa[ef[e]] * 12 + sa[et[e]]];
#pragma unroll
    for (int o = 16; o; o >>= 1) s += __shfl_down_sync(0xffffffffu, s, o);
    if (lane == 0) red[w] = s;

    float ns = (tid < 64) ? snv[tid * 12 + sa[tid]] : 0.f;
    if (w < 2) {
#pragma unroll
        for (int o = 16; o; o >>= 1) ns += __shfl_down_sync(0xffffffffu, ns, o);
        if (lane == 0) red2[w] = ns;
    }
    __syncthreads();

    if (w == 0) {
        float v = red[lane];
#pragma unroll
        for (int o = 16; o; o >>= 1) v += __shfl_down_sync(0xffffffffu, v, o);
        if (lane == 0) {
            float qv = (red2[0] + red2[1]) * (1.f / Nn) + v;   // v pre-scaled by 1/E
            int up = first || (qv > g_qmax[b]);
            if (up) g_qmax[b] = qv;
            out[b] = g_qmax[b];
            flag = up;
        }
    }
    __syncthreads();
    if (flag && tid < 64) out[Bq + b * 64 + tid] = (float)sa[tid];
}

// ---------------------------------------------------------
extern "C" void kernel_launch(void* const* d_in, const int* in_sizes, int n_in,
                              void* d_out, int out_size) {
    const float* obs = (const float*)d_in[0];
    const float* W1n = (const float*)d_in[1];
    const float* b1n = (const float*)d_in[2];
    const float* W2n = (const float*)d_in[3];
    const float* b2n = (const float*)d_in[4];
    const float* W1e = (const float*)d_in[5];
    const float* b1e = (const float*)d_in[6];
    const float* W2e = (const float*)d_in[7];
    const float* b2e = (const float*)d_in[8];
    const int* ef = (const int*)d_in[9];
    const int* et = (const int*)d_in[10];
    float* out = (float*)d_out;

    const int gemm_smem = (18432 + 128 * 68) * 4;   // 108544 B -> 2 blocks/SM
    cudaFuncSetAttribute(k_edge_gemm, cudaFuncAttributeMaxDynamicSharedMemorySize, gemm_smem);

    k_node<<<Bq * Nn / 8, 128>>>(obs, W1n, b1n, W2n, b2n, W1e);                        // idx 0
    k_edge_gemm<<<dim3(Ee / TE, 32), 384, gemm_smem>>>(ef, et, b1e, W2e, b2e, 0);      // idx 1
    k_edge_gemm<<<dim3(Ee / TE, 32), 384, gemm_smem>>>(ef, et, b1e, W2e, b2e, 32);     // idx 2
    k_edge_gemm<<<dim3(Ee / TE, 64), 384, gemm_smem>>>(ef, et, b1e, W2e, b2e, 64);     // idx 3 (profiled)
    k_qe<<<Bq, 1024>>>(ef, et, out, 1);                                                // idx 4
    for (int it = 0; it < NITERS; it++) {
        k_msg<<<dim3(Ee / 32, Bq), 512>>>(ef, et, it == 0);
        k_qe<<<Bq, 1024>>>(ef, et, out, 0);
    }
}

// round 13
// speedup vs baseline: 1.3512x; 1.3512x over previous
#include <cuda_runtime.h>

#define Bq 128
#define Nn 64
#define Dd 64
#define Aa 12
#define Hh 128
#define Ee 4032
#define NITERS 8
#define TE 64   // edges per gemm block

typedef unsigned long long ull;

// -------- device scratch (no allocations allowed) --------
__device__ __align__(16) float g_edge_vals[74317824];   // B*E*A*A, PRE-SCALED by 1/E
__device__ __align__(16) float g_X1[Bq*Nn*Hh];
__device__ __align__(16) float g_X2[Bq*Nn*Hh];
__device__ float g_node_vals[Bq*Nn*Aa];
__device__ float g_q[Bq*Nn*Aa];
__device__ __align__(16) float g_msg_forw[Bq*Ee*Aa];
__device__ __align__(16) float g_msg_back[Bq*Ee*Aa];
__device__ float g_qmax[Bq];

// ---------------------------------------------------------
// K0: node MLP + per-node halves of edge layer-1 (X1, X2)
// ---------------------------------------------------------
__global__ void k_node(const float* __restrict__ obs, const float* __restrict__ W1n,
                       const float* __restrict__ b1n, const float* __restrict__ W2n,
                       const float* __restrict__ b2n, const float* __restrict__ W1e) {
    int row0 = blockIdx.x * 8;
    int t = threadIdx.x;
    __shared__ float so[8][64];
    __shared__ float sh[8][128];
    for (int i = t; i < 512; i += 128) so[i >> 6][i & 63] = obs[row0 * 64 + i];
    __syncthreads();
    for (int r = 0; r < 8; r++) {
        float s1 = b1n[t], x1 = 0.f, x2 = 0.f;
#pragma unroll 8
        for (int d = 0; d < 64; d++) {
            float o = so[r][d];
            s1 = fmaf(o, W1n[d * 128 + t], s1);
            x1 = fmaf(o, W1e[d * 128 + t], x1);
            x2 = fmaf(o, W1e[(64 + d) * 128 + t], x2);
        }
        sh[r][t] = fmaxf(s1, 0.f);
        g_X1[(row0 + r) * 128 + t] = x1;
        g_X2[(row0 + r) * 128 + t] = x2;
    }
    __syncthreads();
    if (t < 96) {
        int r = t / 12, a = t - r * 12;
        float nv = b2n[a];
#pragma unroll 8
        for (int k = 0; k < 128; k++) nv = fmaf(sh[r][k], W2n[k * 12 + a], nv);
        g_node_vals[(row0 + r) * 12 + a] = nv;
    }
}

// ---------------------------------------------------------
// K1: edge layer-2 GEMM, f32x2. 384 thr, 8 rows x 3 STRIDED cols.
// rg=tid/48: hv LDS.64 warp-broadcast (~1 wf each).
// cols {cg, cg+48, cg+96}: each ws load = 32 consecutive floats
// per warp = 1 wavefront. 64-edge tile -> 2 blocks/SM.
// Output pre-scaled by 1/E. Bit-identical math to R9/R10.
// ---------------------------------------------------------
__global__ void __launch_bounds__(384, 2)
k_edge_gemm(const int* __restrict__ ef, const int* __restrict__ et,
            const float* __restrict__ b1e, const float* __restrict__ W2e,
            const float* __restrict__ b2e, int b_off) {
    extern __shared__ float sm[];
    float* Wsh = sm;                 // 128*144 floats
    float* hT  = sm + 18432;         // 128*68 floats (pitch 68)
    __shared__ int sf[TE], st2[TE];
    int b = b_off + blockIdx.y;
    int e0 = blockIdx.x * TE;
    int tid = threadIdx.x;

    if (tid < TE) { sf[tid] = ef[e0 + tid]; st2[tid] = et[e0 + tid]; }
    {
        const float4* W4 = (const float4*)W2e;
        float4* Ws4 = (float4*)Wsh;
        for (int i = tid; i < 4608; i += 384) Ws4[i] = W4[i];
    }
    __syncthreads();

    for (int idx = tid; idx < 8192; idx += 384) {
        int el = idx >> 7, k = idx & 127;
        float v = g_X1[(b * Nn + sf[el]) * Hh + k] + g_X2[(b * Nn + st2[el]) * Hh + k] + b1e[k];
        hT[k * 68 + el] = fmaxf(v, 0.f);
    }
    __syncthreads();

    int rg = tid / 48;     // rows rg*8 .. rg*8+7  (warp-uniform -> hv broadcast)
    int cg = tid % 48;     // cols cg, cg+48, cg+96 (lane-consecutive -> ws coalesced)

    ull acc[4][3];
#pragma unroll
    for (int j = 0; j < 4; j++)
#pragma unroll
        for (int c = 0; c < 3; c++) acc[j][c] = 0ull;

    const float* hbase = hT + rg * 8;
    const float* wbase = Wsh + cg;

    ull hv[2][4]; float ws[2][3];
#pragma unroll
    for (int j = 0; j < 4; j++) hv[0][j] = *(const ull*)(hbase + 2 * j);
#pragma unroll
    for (int c = 0; c < 3; c++) ws[0][c] = wbase[c * 48];

#pragma unroll 8
    for (int k = 0; k < 128; k++) {
        int cur = k & 1, nxt = cur ^ 1;
        if (k < 127) {
#pragma unroll
            for (int j = 0; j < 4; j++) hv[nxt][j] = *(const ull*)(hbase + (k + 1) * 68 + 2 * j);
#pragma unroll
            for (int c = 0; c < 3; c++) ws[nxt][c] = wbase[(k + 1) * 144 + c * 48];
        }
        ull wv[3];
#pragma unroll
        for (int c = 0; c < 3; c++)
            asm("mov.b64 %0, {%1, %1};" : "=l"(wv[c]) : "f"(ws[cur][c]));
#pragma unroll
        for (int c = 0; c < 3; c++) {
            asm("fma.rn.f32x2 %0, %1, %2, %0;" : "+l"(acc[0][c]) : "l"(hv[cur][0]), "l"(wv[c]));
            asm("fma.rn.f32x2 %0, %1, %2, %0;" : "+l"(acc[1][c]) : "l"(hv[cur][1]), "l"(wv[c]));
            asm("fma.rn.f32x2 %0, %1, %2, %0;" : "+l"(acc[2][c]) : "l"(hv[cur][2]), "l"(wv[c]));
            asm("fma.rn.f32x2 %0, %1, %2, %0;" : "+l"(acc[3][c]) : "l"(hv[cur][3]), "l"(wv[c]));
        }
    }

    float bb[3];
#pragma unroll
    for (int c = 0; c < 3; c++) bb[c] = b2e[cg + c * 48];
    const float invE = 1.f / Ee;

    size_t base = ((size_t)b * Ee + e0) * 144 + cg;
#pragma unroll
    for (int j = 0; j < 4; j++) {
        int row = rg * 8 + 2 * j;
#pragma unroll
        for (int c = 0; c < 3; c++) {
            float lo, hi;
            asm("mov.b64 {%0, %1}, %2;" : "=f"(lo), "=f"(hi) : "l"(acc[j][c]));
            g_edge_vals[base + (size_t)row * 144 + c * 48]       = (lo + bb[c]) * invE;
            g_edge_vals[base + (size_t)(row + 1) * 144 + c * 48] = (hi + bb[c]) * invE;
        }
    }
}

// ---------------------------------------------------------
// K4: message update, register/shuffle version (R7, measured 89us).
// ---------------------------------------------------------
__global__ void __launch_bounds__(512)
k_msg(const int* __restrict__ ef, const int* __restrict__ et, int first) {
    __shared__ float sev[32 * 144 + 160];
    int b = blockIdx.y;
    int tid = threadIdx.x;
    int elb = tid >> 4;
    int sub = tid & 15;
    int e = blockIdx.x * 32 + elb;
    unsigned g = (tid & 31) & ~15u;

    size_t evbase = ((size_t)b * Ee + e) * 144;
    size_t mi = ((size_t)b * Ee + e) * 12 + sub;
    float r[12];
    float su = 0.f, sv = 0.f;
    if (sub < 12) {
        float4 r0 = *(const float4*)&g_edge_vals[evbase + sub * 12];
        float4 r1 = *(const float4*)&g_edge_vals[evbase + sub * 12 + 4];
        float4 r2 = *(const float4*)&g_edge_vals[evbase + sub * 12 + 8];
        r[0]=r0.x; r[1]=r0.y; r[2]=r0.z; r[3]=r0.w;
        r[4]=r1.x; r[5]=r1.y; r[6]=r1.z; r[7]=r1.w;
        r[8]=r2.x; r[9]=r2.y; r[10]=r2.z; r[11]=r2.w;
        int f = ef[e], t = et[e];
        su = g_q[(b * Nn + f) * 12 + sub];
        sv = g_q[(b * Nn + t) * 12 + sub];
        if (!first) { su -= g_msg_back[mi]; sv -= g_msg_forw[mi]; }
        float4* sp = (float4*)&sev[elb * 144 + sub * 12];
        sp[0] = r0; sp[1] = r1; sp[2] = r2;
    } else {
#pragma unroll
        for (int x = 0; x < 12; x++) r[x] = 0.f;
    }
    __syncwarp();

    float mf = -3.4e38f, mb = -3.4e38f;
    const float* colp = &sev[elb * 144 + sub];
#pragma unroll
    for (int x = 0; x < 12; x++) {
        float sux = __shfl_sync(0xffffffffu, su, g + x);
        float svx = __shfl_sync(0xffffffffu, sv, g + x);
        mb = fmaxf(mb, svx + r[x]);
        mf = fmaxf(mf, sux + colp[x * 12]);
    }
    float sf = (sub < 12) ? mf : 0.f;
    float sb = (sub < 12) ? mb : 0.f;
#pragma unroll
    for (int o = 8; o; o >>= 1) {
        sf += __shfl_xor_sync(0xffffffffu, sf, o);
        sb += __shfl_xor_sync(0xffffffffu, sb, o);
    }
    if (sub < 12) {
        g_msg_forw[mi] = mf - sf * (1.f / 12.f);
        g_msg_back[mi] = mb - sb * (1.f / 12.f);
    }
}

// ---------------------------------------------------------
// K5: fused q-update + argmax + eval (shuffle reductions, 16us).
// ---------------------------------------------------------
__global__ void __launch_bounds__(1024)
k_qe(const int* __restrict__ ef, const int* __restrict__ et,
     float* __restrict__ out, int first) {
    int b = blockIdx.x, tid = threadIdx.x;
    int w = tid >> 5, lane = tid & 31;
    __shared__ float snv[768];
    __shared__ int sa[64];
    __shared__ float red[32];
    __shared__ float red2[2];
    __shared__ int flag;
    for (int i = tid; i < 768; i += 1024) snv[i] = g_node_vals[b * 768 + i];
    __syncthreads();

    if (first) {
        if (tid < 768) g_q[b * 768 + tid] = snv[tid] * (1.f / Nn);
        if (tid < 64) {
            float best = -3.4e38f; int ba = 0;
#pragma unroll
            for (int a = 0; a < 12; a++) {
                float v = snv[tid * 12 + a];
                if (v > best) { best = v; ba = a; }
            }
            sa[tid] = ba;
        }
    } else {
#pragma unroll
        for (int nn = 0; nn < 2; nn++) {
            int n = w * 2 + nn;
            float acc[12];
#pragma unroll
            for (int a = 0; a < 12; a++) acc[a] = 0.f;

            size_t mbb = ((size_t)b * Ee + n * 63) * 12;
            for (int m = lane; m < 63; m += 32) {
                const float4* p = (const float4*)&g_msg_back[mbb + m * 12];
                float4 p0 = p[0], p1 = p[1], p2 = p[2];
                acc[0] += p0.x; acc[1] += p0.y; acc[2]  += p0.z; acc[3]  += p0.w;
                acc[4] += p1.x; acc[5] += p1.y; acc[6]  += p1.z; acc[7]  += p1.w;
                acc[8] += p2.x; acc[9] += p2.y; acc[10] += p2.z; acc[11] += p2.w;
            }
            for (int i = lane; i < 64; i += 32) {
                if (i == n) continue;
                int e = i * 63 + n - (n > i ? 1 : 0);
                const float4* p = (const float4*)&g_msg_forw[((size_t)b * Ee + e) * 12];
                float4 p0 = p[0], p1 = p[1], p2 = p[2];
                acc[0] += p0.x; acc[1] += p0.y; acc[2]  += p0.z; acc[3]  += p0.w;
                acc[4] += p1.x; acc[5] += p1.y; acc[6]  += p1.z; acc[7]  += p1.w;
                acc[8] += p2.x; acc[9] += p2.y; acc[10] += p2.z; acc[11] += p2.w;
            }
#pragma unroll
            for (int off = 16; off; off >>= 1)
#pragma unroll
                for (int a = 0; a < 12; a++) acc[a] += __shfl_down_sync(0xffffffffu, acc[a], off);

            if (lane == 0) {
                float best = -3.4e38f; int ba = 0;
#pragma unroll
                for (int a = 0; a < 12; a++) {
                    float qa = snv[n * 12 + a] * (1.f / Nn) + acc[a];
                    g_q[(b * 64 + n) * 12 + a] = qa;
                    if (qa > best) { best = qa; ba = a; }
                }
                sa[n] = ba;
            }
        }
    }
    __syncthreads();

    float s = 0.f;
#pragma unroll
    for (int e = tid; e < Ee; e += 1024)
        s += g_edge_vals[((size_t)b * Ee + e) * 144 + sa[ef[e]] * 12 + sa[et[e]]];
#pragma unroll
    for (int o = 16; o; o >>= 1) s += __shfl_down_sync(0xffffffffu, s, o);
    if (lane == 0) red[w] = s;

    float ns = (tid < 64) ? snv[tid * 12 + sa[tid]] : 0.f;
    if (w < 2) {
#pragma unroll
        for (int o = 16; o; o >>= 1) ns += __shfl_down_sync(0xffffffffu, ns, o);
        if (lane == 0) red2[w] = ns;
    }
    __syncthreads();

    if (w == 0) {
        float v = red[lane];
#pragma unroll
        for (int o = 16; o; o >>= 1) v += __shfl_down_sync(0xffffffffu, v, o);
        if (lane == 0) {
            float qv = (red2[0] + red2[1]) * (1.f / Nn) + v;   // v pre-scaled by 1/E
            int up = first || (qv > g_qmax[b]);
            if (up) g_qmax[b] = qv;
            out[b] = g_qmax[b];
            flag = up;
        }
    }
    __syncthreads();
    if (flag && tid < 64) out[Bq + b * 64 + tid] = (float)sa[tid];
}

// ---------------------------------------------------------
extern "C" void kernel_launch(void* const* d_in, const int* in_sizes, int n_in,
                              void* d_out, int out_size) {
    const float* obs = (const float*)d_in[0];
    const float* W1n = (const float*)d_in[1];
    const float* b1n = (const float*)d_in[2];
    const float* W2n = (const float*)d_in[3];
    const float* b2n = (const float*)d_in[4];
    const float* W1e = (const float*)d_in[5];
    const float* b1e = (const float*)d_in[6];
    const float* W2e = (const float*)d_in[7];
    const float* b2e = (const float*)d_in[8];
    const int* ef = (const int*)d_in[9];
    const int* et = (const int*)d_in[10];
    float* out = (float*)d_out;

    const int gemm_smem = (18432 + 128 * 68) * 4;   // 108544 B -> 2 blocks/SM
    cudaFuncSetAttribute(k_edge_gemm, cudaFuncAttributeMaxDynamicSharedMemorySize, gemm_smem);

    k_node<<<Bq * Nn / 8, 128>>>(obs, W1n, b1n, W2n, b2n, W1e);                        // idx 0
    k_edge_gemm<<<dim3(Ee / TE, 32), 384, gemm_smem>>>(ef, et, b1e, W2e, b2e, 0);      // idx 1
    k_edge_gemm<<<dim3(Ee / TE, 32), 384, gemm_smem>>>(ef, et, b1e, W2e, b2e, 32);     // idx 2
    k_edge_gemm<<<dim3(Ee / TE, 64), 384, gemm_smem>>>(ef, et, b1e, W2e, b2e, 64);     // idx 3 (profiled)
    k_qe<<<Bq, 1024>>>(ef, et, out, 1);                                                // idx 4
    for (int it = 0; it < NITERS; it++) {
        k_msg<<<dim3(Ee / 32, Bq), 512>>>(ef, et, it == 0);
        k_qe<<<Bq, 1024>>>(ef, et, out, 0);
    }
}

// round 14
// speedup vs baseline: 1.4193x; 1.0504x over previous
#include <cuda_runtime.h>

#define Bq 128
#define Nn 64
#define Dd 64
#define Aa 12
#define Hh 128
#define Ee 4032
#define NITERS 8
#define TE 64   // edges per gemm block

typedef unsigned long long ull;

// -------- device scratch (no allocations allowed) --------
__device__ __align__(16) float g_edge_vals[74317824];   // B*E*A*A, PRE-SCALED by 1/E
__device__ __align__(16) float g_X1[Bq*Nn*Hh];
__device__ __align__(16) float g_X2[Bq*Nn*Hh];
__device__ float g_node_vals[Bq*Nn*Aa];
__device__ float g_q[Bq*Nn*Aa];
__device__ __align__(16) float g_msg_forw[Bq*Ee*Aa];
__device__ __align__(16) float g_msg_back[Bq*Ee*Aa];
__device__ float g_qmax[Bq];

// ---------------------------------------------------------
// K0: node MLP + per-node halves of edge layer-1 (X1, X2)
// ---------------------------------------------------------
__global__ void k_node(const float* __restrict__ obs, const float* __restrict__ W1n,
                       const float* __restrict__ b1n, const float* __restrict__ W2n,
                       const float* __restrict__ b2n, const float* __restrict__ W1e) {
    int row0 = blockIdx.x * 8;
    int t = threadIdx.x;
    __shared__ float so[8][64];
    __shared__ float sh[8][128];
    for (int i = t; i < 512; i += 128) so[i >> 6][i & 63] = obs[row0 * 64 + i];
    __syncthreads();
    for (int r = 0; r < 8; r++) {
        float s1 = b1n[t], x1 = 0.f, x2 = 0.f;
#pragma unroll 8
        for (int d = 0; d < 64; d++) {
            float o = so[r][d];
            s1 = fmaf(o, W1n[d * 128 + t], s1);
            x1 = fmaf(o, W1e[d * 128 + t], x1);
            x2 = fmaf(o, W1e[(64 + d) * 128 + t], x2);
        }
        sh[r][t] = fmaxf(s1, 0.f);
        g_X1[(row0 + r) * 128 + t] = x1;
        g_X2[(row0 + r) * 128 + t] = x2;
    }
    __syncthreads();
    if (t < 96) {
        int r = t / 12, a = t - r * 12;
        float nv = b2n[a];
#pragma unroll 8
        for (int k = 0; k < 128; k++) nv = fmaf(sh[r][k], W2n[k * 12 + a], nv);
        g_node_vals[(row0 + r) * 12 + a] = nv;
    }
}

// ---------------------------------------------------------
// K1: edge layer-2 GEMM (R13 config, measured 305us/64 batches).
// rg=tid/48 (hv broadcast), strided cols {cg,cg+48,cg+96} (ws 1-wf).
// ---------------------------------------------------------
__global__ void __launch_bounds__(384, 2)
k_edge_gemm(const int* __restrict__ ef, const int* __restrict__ et,
            const float* __restrict__ b1e, const float* __restrict__ W2e,
            const float* __restrict__ b2e, int b_off) {
    extern __shared__ float sm[];
    float* Wsh = sm;                 // 128*144 floats
    float* hT  = sm + 18432;         // 128*68 floats (pitch 68)
    __shared__ int sf[TE], st2[TE];
    int b = b_off + blockIdx.y;
    int e0 = blockIdx.x * TE;
    int tid = threadIdx.x;

    if (tid < TE) { sf[tid] = ef[e0 + tid]; st2[tid] = et[e0 + tid]; }
    {
        const float4* W4 = (const float4*)W2e;
        float4* Ws4 = (float4*)Wsh;
        for (int i = tid; i < 4608; i += 384) Ws4[i] = W4[i];
    }
    __syncthreads();

    for (int idx = tid; idx < 8192; idx += 384) {
        int el = idx >> 7, k = idx & 127;
        float v = g_X1[(b * Nn + sf[el]) * Hh + k] + g_X2[(b * Nn + st2[el]) * Hh + k] + b1e[k];
        hT[k * 68 + el] = fmaxf(v, 0.f);
    }
    __syncthreads();

    int rg = tid / 48;
    int cg = tid % 48;

    ull acc[4][3];
#pragma unroll
    for (int j = 0; j < 4; j++)
#pragma unroll
        for (int c = 0; c < 3; c++) acc[j][c] = 0ull;

    const float* hbase = hT + rg * 8;
    const float* wbase = Wsh + cg;

    ull hv[2][4]; float ws[2][3];
#pragma unroll
    for (int j = 0; j < 4; j++) hv[0][j] = *(const ull*)(hbase + 2 * j);
#pragma unroll
    for (int c = 0; c < 3; c++) ws[0][c] = wbase[c * 48];

#pragma unroll 8
    for (int k = 0; k < 128; k++) {
        int cur = k & 1, nxt = cur ^ 1;
        if (k < 127) {
#pragma unroll
            for (int j = 0; j < 4; j++) hv[nxt][j] = *(const ull*)(hbase + (k + 1) * 68 + 2 * j);
#pragma unroll
            for (int c = 0; c < 3; c++) ws[nxt][c] = wbase[(k + 1) * 144 + c * 48];
        }
        ull wv[3];
#pragma unroll
        for (int c = 0; c < 3; c++)
            asm("mov.b64 %0, {%1, %1};" : "=l"(wv[c]) : "f"(ws[cur][c]));
#pragma unroll
        for (int c = 0; c < 3; c++) {
            asm("fma.rn.f32x2 %0, %1, %2, %0;" : "+l"(acc[0][c]) : "l"(hv[cur][0]), "l"(wv[c]));
            asm("fma.rn.f32x2 %0, %1, %2, %0;" : "+l"(acc[1][c]) : "l"(hv[cur][1]), "l"(wv[c]));
            asm("fma.rn.f32x2 %0, %1, %2, %0;" : "+l"(acc[2][c]) : "l"(hv[cur][2]), "l"(wv[c]));
            asm("fma.rn.f32x2 %0, %1, %2, %0;" : "+l"(acc[3][c]) : "l"(hv[cur][3]), "l"(wv[c]));
        }
    }

    float bb[3];
#pragma unroll
    for (int c = 0; c < 3; c++) bb[c] = b2e[cg + c * 48];
    const float invE = 1.f / Ee;

    size_t base = ((size_t)b * Ee + e0) * 144 + cg;
#pragma unroll
    for (int j = 0; j < 4; j++) {
        int row = rg * 8 + 2 * j;
#pragma unroll
        for (int c = 0; c < 3; c++) {
            float lo, hi;
            asm("mov.b64 {%0, %1}, %2;" : "=f"(lo), "=f"(hi) : "l"(acc[j][c]));
            g_edge_vals[base + (size_t)row * 144 + c * 48]       = (lo + bb[c]) * invE;
            g_edge_vals[base + (size_t)(row + 1) * 144 + c * 48] = (hi + bb[c]) * invE;
        }
    }
}

// ---------------------------------------------------------
// K4: message update, no-smem version. Columns read directly
// from global (L1-hot from the row loads of sibling lanes):
// removes the STS staging (27 wf/warp) and __syncwarp.
// ---------------------------------------------------------
__global__ void __launch_bounds__(512)
k_msg(const int* __restrict__ ef, const int* __restrict__ et, int first) {
    int b = blockIdx.y;
    int tid = threadIdx.x;
    int elb = tid >> 4;
    int sub = tid & 15;
    int e = blockIdx.x * 32 + elb;
    unsigned g = (tid & 31) & ~15u;
    int subc = (sub < 12) ? sub : 0;   // pad lanes read lane-0 column (discarded)

    size_t evbase = ((size_t)b * Ee + e) * 144;
    size_t mi = ((size_t)b * Ee + e) * 12 + sub;
    float r[12];
    float su = 0.f, sv = 0.f;
    if (sub < 12) {
        float4 r0 = *(const float4*)&g_edge_vals[evbase + sub * 12];
        float4 r1 = *(const float4*)&g_edge_vals[evbase + sub * 12 + 4];
        float4 r2 = *(const float4*)&g_edge_vals[evbase + sub * 12 + 8];
        r[0]=r0.x; r[1]=r0.y; r[2]=r0.z; r[3]=r0.w;
        r[4]=r1.x; r[5]=r1.y; r[6]=r1.z; r[7]=r1.w;
        r[8]=r2.x; r[9]=r2.y; r[10]=r2.z; r[11]=r2.w;
        int f = ef[e], t = et[e];
        su = g_q[(b * Nn + f) * 12 + sub];
        sv = g_q[(b * Nn + t) * 12 + sub];
        if (!first) { su -= g_msg_back[mi]; sv -= g_msg_forw[mi]; }
    } else {
#pragma unroll
        for (int x = 0; x < 12; x++) r[x] = 0.f;
    }

    const float* __restrict__ colg = &g_edge_vals[evbase + subc];
    float mf = -3.4e38f, mb = -3.4e38f;
#pragma unroll
    for (int x = 0; x < 12; x++) {
        float sux = __shfl_sync(0xffffffffu, su, g + x);
        float svx = __shfl_sync(0xffffffffu, sv, g + x);
        mb = fmaxf(mb, svx + r[x]);
        mf = fmaxf(mf, sux + colg[x * 12]);   // same values the old smem path held
    }
    float sf = (sub < 12) ? mf : 0.f;
    float sb = (sub < 12) ? mb : 0.f;
#pragma unroll
    for (int o = 8; o; o >>= 1) {
        sf += __shfl_xor_sync(0xffffffffu, sf, o);
        sb += __shfl_xor_sync(0xffffffffu, sb, o);
    }
    if (sub < 12) {
        g_msg_forw[mi] = mf - sf * (1.f / 12.f);
        g_msg_back[mi] = mb - sb * (1.f / 12.f);
    }
}

// ---------------------------------------------------------
// K5: fused q-update + argmax + eval (shuffle reductions, 16us).
// ---------------------------------------------------------
__global__ void __launch_bounds__(1024)
k_qe(const int* __restrict__ ef, const int* __restrict__ et,
     float* __restrict__ out, int first) {
    int b = blockIdx.x, tid = threadIdx.x;
    int w = tid >> 5, lane = tid & 31;
    __shared__ float snv[768];
    __shared__ int sa[64];
    __shared__ float red[32];
    __shared__ float red2[2];
    __shared__ int flag;
    for (int i = tid; i < 768; i += 1024) snv[i] = g_node_vals[b * 768 + i];
    __syncthreads();

    if (first) {
        if (tid < 768) g_q[b * 768 + tid] = snv[tid] * (1.f / Nn);
        if (tid < 64) {
            float best = -3.4e38f; int ba = 0;
#pragma unroll
            for (int a = 0; a < 12; a++) {
                float v = snv[tid * 12 + a];
                if (v > best) { best = v; ba = a; }
            }
            sa[tid] = ba;
        }
    } else {
#pragma unroll
        for (int nn = 0; nn < 2; nn++) {
            int n = w * 2 + nn;
            float acc[12];
#pragma unroll
            for (int a = 0; a < 12; a++) acc[a] = 0.f;

            size_t mbb = ((size_t)b * Ee + n * 63) * 12;
            for (int m = lane; m < 63; m += 32) {
                const float4* p = (const float4*)&g_msg_back[mbb + m * 12];
                float4 p0 = p[0], p1 = p[1], p2 = p[2];
                acc[0] += p0.x; acc[1] += p0.y; acc[2]  += p0.z; acc[3]  += p0.w;
                acc[4] += p1.x; acc[5] += p1.y; acc[6]  += p1.z; acc[7]  += p1.w;
                acc[8] += p2.x; acc[9] += p2.y; acc[10] += p2.z; acc[11] += p2.w;
            }
            for (int i = lane; i < 64; i += 32) {
                if (i == n) continue;
                int e = i * 63 + n - (n > i ? 1 : 0);
                const float4* p = (const float4*)&g_msg_forw[((size_t)b * Ee + e) * 12];
                float4 p0 = p[0], p1 = p[1], p2 = p[2];
                acc[0] += p0.x; acc[1] += p0.y; acc[2]  += p0.z; acc[3]  += p0.w;
                acc[4] += p1.x; acc[5] += p1.y; acc[6]  += p1.z; acc[7]  += p1.w;
                acc[8] += p2.x; acc[9] += p2.y; acc[10] += p2.z; acc[11] += p2.w;
            }
#pragma unroll
            for (int off = 16; off; off >>= 1)
#pragma unroll
                for (int a = 0; a < 12; a++) acc[a] += __shfl_down_sync(0xffffffffu, acc[a], off);

            if (lane == 0) {
                float best = -3.4e38f; int ba = 0;
#pragma unroll
                for (int a = 0; a < 12; a++) {
                    float qa = snv[n * 12 + a] * (1.f / Nn) + acc[a];
                    g_q[(b * 64 + n) * 12 + a] = qa;
                    if (qa > best) { best = qa; ba = a; }
                }
                sa[n] = ba;
            }
        }
    }
    __syncthreads();

    float s = 0.f;
#pragma unroll
    for (int e = tid; e < Ee; e += 1024)
        s += g_edge_vals[((size_t)b * Ee + e) * 144 + sa[ef[e]] * 12 + sa[et[e]]];
#pragma unroll
    for (int o = 16; o; o >>= 1) s += __shfl_down_sync(0xffffffffu, s, o);
    if (lane == 0) red[w] = s;

    float ns = (tid < 64) ? snv[tid * 12 + sa[tid]] : 0.f;
    if (w < 2) {
#pragma unroll
        for (int o = 16; o; o >>= 1) ns += __shfl_down_sync(0xffffffffu, ns, o);
        if (lane == 0) red2[w] = ns;
    }
    __syncthreads();

    if (w == 0) {
        float v = red[lane];
#pragma unroll
        for (int o = 16; o; o >>= 1) v += __shfl_down_sync(0xffffffffu, v, o);
        if (lane == 0) {
            float qv = (red2[0] + red2[1]) * (1.f / Nn) + v;   // v pre-scaled by 1/E
            int up = first || (qv > g_qmax[b]);
            if (up) g_qmax[b] = qv;
            out[b] = g_qmax[b];
            flag = up;
        }
    }
    __syncthreads();
    if (flag && tid < 64) out[Bq + b * 64 + tid] = (float)sa[tid];
}

// ---------------------------------------------------------
extern "C" void kernel_launch(void* const* d_in, const int* in_sizes, int n_in,
                              void* d_out, int out_size) {
    const float* obs = (const float*)d_in[0];
    const float* W1n = (const float*)d_in[1];
    const float* b1n = (const float*)d_in[2];
    const float* W2n = (const float*)d_in[3];
    const float* b2n = (const float*)d_in[4];
    const float* W1e = (const float*)d_in[5];
    const float* b1e = (const float*)d_in[6];
    const float* W2e = (const float*)d_in[7];
    const float* b2e = (const float*)d_in[8];
    const int* ef = (const int*)d_in[9];
    const int* et = (const int*)d_in[10];
    float* out = (float*)d_out;

    const int gemm_smem = (18432 + 128 * 68) * 4;   // 108544 B -> 2 blocks/SM
    cudaFuncSetAttribute(k_edge_gemm, cudaFuncAttributeMaxDynamicSharedMemorySize, gemm_smem);

    k_node<<<Bq * Nn / 8, 128>>>(obs, W1n, b1n, W2n, b2n, W1e);                        // idx 0
    k_edge_gemm<<<dim3(Ee / TE, Bq), 384, gemm_smem>>>(ef, et, b1e, W2e, b2e, 0);      // idx 1 (merged)
    k_qe<<<Bq, 1024>>>(ef, et, out, 1);                                                // idx 2
    for (int it = 0; it < NITERS; it++) {
        k_msg<<<dim3(Ee / 32, Bq), 512>>>(ef, et, it == 0);                            // idx 3 (profiled, first)
        k_qe<<<Bq, 1024>>>(ef, et, out, 0);
    }
}